// round 6
// baseline (speedup 1.0000x reference)
#include <cuda_runtime.h>
#include <cstdint>

#define NTASKS 64
#define NROWS  2048
#define INSZ   512
#define OUTSZ  512
#define MT     64          // M rows per CTA tile
#define NTILE  128         // N cols per CTA
#define KT     64          // K per stage tile
#define THREADS 256

// SMEM (floats). Pads chosen for conflict-free scalar fragment LDS.
#define AS 68              // A row stride: 64 k + 4 pad  (68 mod 32 == 4)
#define BS 136             // B row stride: 128 n + 8 pad (136 mod 32 == 8)
#define A_BYTES (MT * AS * 4)        // 17408
#define STAGE   (A_BYTES + KT * BS * 4)  // 17408 + 34816 = 52224
#define SMEM_TOTAL (2 * STAGE)       // 104448 -> 2 CTAs/SM

__device__ int g_row_order[NROWS];
__device__ int g_task_off[NTASKS + 1];

// ---------------- helpers ----------------
__device__ __forceinline__ uint32_t smem_u32(const void* p) {
    uint32_t a;
    asm("{ .reg .u64 t; cvta.to.shared.u64 t, %1; cvt.u32.u64 %0, t; }" : "=r"(a) : "l"(p));
    return a;
}
__device__ __forceinline__ uint32_t tf32(float x) {
    uint32_t d;
    asm("cvt.rna.tf32.f32 %0, %1;" : "=r"(d) : "f"(x));
    return d;
}
__device__ __forceinline__ void sts128(uint32_t a, uint32_t x, uint32_t y, uint32_t z, uint32_t w) {
    asm volatile("st.shared.v4.b32 [%0], {%1,%2,%3,%4};"
                 :: "r"(a), "r"(x), "r"(y), "r"(z), "r"(w) : "memory");
}
__device__ __forceinline__ uint32_t lds32(uint32_t a) {
    uint32_t v;
    asm volatile("ld.shared.b32 %0, [%1];" : "=r"(v) : "r"(a));
    return v;
}
__device__ __forceinline__ void mma16888(float* c, const uint32_t* a, const uint32_t* b) {
    asm volatile("mma.sync.aligned.m16n8k8.row.col.f32.tf32.tf32.f32 "
                 "{%0,%1,%2,%3}, {%4,%5,%6,%7}, {%8,%9}, {%0,%1,%2,%3};"
                 : "+f"(c[0]), "+f"(c[1]), "+f"(c[2]), "+f"(c[3])
                 : "r"(a[0]), "r"(a[1]), "r"(a[2]), "r"(a[3]), "r"(b[0]), "r"(b[1]));
}

// ---------------------------------------------------------------------------
// Kernel 1: counting sort by task (parallel warp-scan prefix).
// ---------------------------------------------------------------------------
__global__ void sort_rows_kernel(const void* __restrict__ task_ids_raw) {
    __shared__ int counts[NTASKS], scan[NTASKS], cursor[NTASKS];
    __shared__ int wtot, is64;
    const int tid = threadIdx.x;
    if (tid < NTASKS) counts[tid] = 0;
    if (tid == 0) is64 = 1;
    __syncthreads();
    const int* as32 = (const int*)task_ids_raw;
    int nz = 0;
    for (int i = tid; i < NROWS / 2; i += THREADS)
        if (as32[2 * i + 1] != 0) nz = 1;
    if (nz) atomicExch(&is64, 0);
    __syncthreads();
    const int wide = is64;
    for (int i = tid; i < NROWS; i += THREADS)
        atomicAdd(&counts[wide ? as32[2 * i] : as32[i]], 1);
    __syncthreads();
    if (tid < NTASKS) {
        const int lane = tid & 31;
        int s = counts[tid];
        #pragma unroll
        for (int d = 1; d < 32; d <<= 1) {
            int v = __shfl_up_sync(0xFFFFFFFF, s, d);
            if (lane >= d) s += v;
        }
        if (tid == 31) wtot = s;
        scan[tid] = s;
    }
    __syncthreads();
    if (tid < NTASKS) {
        int excl = scan[tid] + ((tid >= 32) ? wtot : 0) - counts[tid];
        cursor[tid] = excl;
        g_task_off[tid] = excl;
    }
    if (tid == 0) g_task_off[NTASKS] = NROWS;
    __syncthreads();
    for (int i = tid; i < NROWS; i += THREADS) {
        int t = wide ? as32[2 * i] : as32[i];
        g_row_order[atomicAdd(&cursor[t], 1)] = i;
    }
}

// ---------------------------------------------------------------------------
// Kernel 2: single-term tf32 GEMM via mma.sync.m16n8k8.tf32.
// grid = (4, 64), 256 threads, 2 CTAs/SM. CTA tile 64m x 128n, K dbl-buffered.
// A SMEM [m][k] stride 68; B SMEM [k][n] stride 136. Scalar-LDS fragments.
// ---------------------------------------------------------------------------
__global__ __launch_bounds__(THREADS, 2)
void task_gemm_tf32(const float* __restrict__ X, const float* __restrict__ W,
                    float* __restrict__ Out) {
    extern __shared__ __align__(16) char smem[];
    const uint32_t sb = smem_u32(smem);

    const int t    = blockIdx.y;
    const int r0   = g_task_off[t];
    const int r1   = g_task_off[t + 1];
    if (r0 >= r1) return;
    const int col0 = blockIdx.x * NTILE;

    const int tid = threadIdx.x, lane = tid & 31, wid = tid >> 5;
    // load roles
    const int am = tid >> 2;           // A row 0..63, also B k-row
    const int aq = tid & 3;            // A k-quad (16 floats) / B n-quad (32 floats)

    const float* __restrict__ Wt = W + (size_t)t * INSZ * OUTSZ + col0;

    // compute roles: 8 warps = 2m x 4n, warp tile 32m x 32n
    const int m0w = (wid & 1) * 32;
    const int n0w = (wid >> 1) * 32;
    const int g8  = lane >> 2;         // groupID 0..7
    const int t4  = lane & 3;          // threadID in group 0..3

    for (int base = r0; base < r1; base += MT) {
        const int nrows = min(MT, r1 - base);
        const bool avalid = am < nrows;
        const float* __restrict__ aptr =
            avalid ? (X + (size_t)g_row_order[base + am] * INSZ + aq * 16) : X;

        float4 pa[4], pb[8];
        auto ldg_tile = [&](int kt) {
            if (avalid) {
                #pragma unroll
                for (int j = 0; j < 4; j++)
                    pa[j] = *(const float4*)(aptr + kt * KT + j * 4);
            } else {
                #pragma unroll
                for (int j = 0; j < 4; j++) pa[j] = make_float4(0.f, 0.f, 0.f, 0.f);
            }
            const float* br = Wt + (size_t)(kt * KT + am) * OUTSZ + aq * 32;
            #pragma unroll
            for (int j = 0; j < 8; j++)
                pb[j] = *(const float4*)(br + j * 4);
        };
        auto sts_tile = [&](int s) {
            const uint32_t stg = sb + s * STAGE;
            const uint32_t ao = stg + (am * AS + aq * 16) * 4;
            #pragma unroll
            for (int j = 0; j < 4; j++)
                sts128(ao + j * 16, tf32(pa[j].x), tf32(pa[j].y), tf32(pa[j].z), tf32(pa[j].w));
            const uint32_t bo = stg + A_BYTES + (am * BS + aq * 32) * 4;
            #pragma unroll
            for (int j = 0; j < 8; j++)
                sts128(bo + j * 16, tf32(pb[j].x), tf32(pb[j].y), tf32(pb[j].z), tf32(pb[j].w));
        };

        float acc[2][4][4];
        #pragma unroll
        for (int i = 0; i < 2; i++)
            #pragma unroll
            for (int j = 0; j < 4; j++)
                #pragma unroll
                for (int q = 0; q < 4; q++) acc[i][j][q] = 0.f;

        ldg_tile(0);
        sts_tile(0);
        __syncthreads();

        for (int kt = 0; kt < INSZ / KT; kt++) {
            if (kt < 7) ldg_tile(kt + 1);

            const uint32_t stg = sb + (kt & 1) * STAGE;
            const uint32_t bbase = stg + A_BYTES;
            #pragma unroll
            for (int ks = 0; ks < 8; ks++) {
                const int k0 = ks * 8;
                uint32_t af[2][4], bf[4][2];
                #pragma unroll
                for (int mt = 0; mt < 2; mt++) {
                    const uint32_t r = stg + ((m0w + mt * 16 + g8) * AS + k0 + t4) * 4;
                    af[mt][0] = lds32(r);
                    af[mt][1] = lds32(r + 8 * AS * 4);
                    af[mt][2] = lds32(r + 16);
                    af[mt][3] = lds32(r + 8 * AS * 4 + 16);
                }
                #pragma unroll
                for (int nf = 0; nf < 4; nf++) {
                    const uint32_t r = bbase + ((k0 + t4) * BS + n0w + nf * 8 + g8) * 4;
                    bf[nf][0] = lds32(r);
                    bf[nf][1] = lds32(r + 4 * BS * 4);
                }
                #pragma unroll
                for (int mt = 0; mt < 2; mt++)
                    #pragma unroll
                    for (int nf = 0; nf < 4; nf++)
                        mma16888(acc[mt][nf], af[mt], bf[nf]);
            }
            if (kt < 7) sts_tile((kt + 1) & 1);
            __syncthreads();
        }

        // epilogue: C frag m16n8: {c0,c1}@(g8, 2*t4), {c2,c3}@(g8+8, 2*t4)
        #pragma unroll
        for (int mt = 0; mt < 2; mt++) {
            const int ml0 = m0w + mt * 16 + g8;
            const int ml1 = ml0 + 8;
            const int o0 = (ml0 < nrows) ? g_row_order[base + ml0] : -1;
            const int o1 = (ml1 < nrows) ? g_row_order[base + ml1] : -1;
            #pragma unroll
            for (int nf = 0; nf < 4; nf++) {
                const int col = col0 + n0w + nf * 8 + t4 * 2;
                if (o0 >= 0)
                    *(float2*)(Out + (size_t)o0 * OUTSZ + col) =
                        make_float2(acc[mt][nf][0], acc[mt][nf][1]);
                if (o1 >= 0)
                    *(float2*)(Out + (size_t)o1 * OUTSZ + col) =
                        make_float2(acc[mt][nf][2], acc[mt][nf][3]);
            }
        }
    }
}

extern "C" void kernel_launch(void* const* d_in, const int* in_sizes, int n_in,
                              void* d_out, int out_size) {
    const float* X        = (const float*)d_in[0];   // [2048, 512] fp32
    const void*  task_ids = d_in[1];                 // [2048] int64 (or int32)
    const float* W        = (const float*)d_in[2];   // [64, 512, 512] fp32
    float*       Out      = (float*)d_out;           // [2048, 512] fp32

    cudaFuncSetAttribute(task_gemm_tf32, cudaFuncAttributeMaxDynamicSharedMemorySize, SMEM_TOTAL);
    sort_rows_kernel<<<1, THREADS>>>(task_ids);
    dim3 grid(OUTSZ / NTILE, NTASKS);
    task_gemm_tf32<<<grid, THREADS, SMEM_TOTAL>>>(X, W, Out);
}

// round 7
// speedup vs baseline: 1.3865x; 1.3865x over previous
#include <cuda_runtime.h>
#include <cstdint>

#define NTASKS 64
#define NROWS  2048
#define INSZ   512
#define OUTSZ  512
#define MT     64          // M rows per CTA tile
#define NTILE  128         // N cols per CTA
#define KT     64          // K per stage tile
#define THREADS 256

// SMEM strides (floats), conflict-free for LDSM(A)/scalar(B)
#define AS 68              // 68 mod 32 == 4 ; LDSM row step 272B -> 8 distinct 16B lanes
#define BS 136             // 136 mod 32 == 8 ; 4k x 8n lanes -> 32 distinct banks
#define A_BYTES (MT * AS * 4)             // 17408
#define STAGE   (A_BYTES + KT * BS * 4)   // 52224
#define SMEM_TOTAL (2 * STAGE)            // 104448 -> 2 CTAs/SM

__device__ int g_row_order[NROWS];
__device__ int g_task_off[NTASKS + 1];

// ---------------- helpers ----------------
__device__ __forceinline__ uint32_t smem_u32(const void* p) {
    uint32_t a;
    asm("{ .reg .u64 t; cvta.to.shared.u64 t, %1; cvt.u32.u64 %0, t; }" : "=r"(a) : "l"(p));
    return a;
}
__device__ __forceinline__ uint32_t cvt_tf32(uint32_t bits) {
    uint32_t d;
    asm("cvt.rna.tf32.f32 %0, %1;" : "=r"(d) : "f"(__uint_as_float(bits)));
    return d;
}
__device__ __forceinline__ void cpa16(uint32_t dst, const void* src, int nbytes) {
    asm volatile("cp.async.cg.shared.global [%0], [%1], 16, %2;"
                 :: "r"(dst), "l"(src), "r"(nbytes) : "memory");
}
__device__ __forceinline__ void cp_commit() {
    asm volatile("cp.async.commit_group;" ::: "memory");
}
template <int N>
__device__ __forceinline__ void cp_wait() {
    asm volatile("cp.async.wait_group %0;" :: "n"(N) : "memory");
}
__device__ __forceinline__ uint32_t lds32(uint32_t a) {
    uint32_t v;
    asm volatile("ld.shared.b32 %0, [%1];" : "=r"(v) : "r"(a));
    return v;
}
__device__ __forceinline__ void ldm_x4(uint32_t* r, uint32_t a) {
    asm volatile("ldmatrix.sync.aligned.m8n8.x4.shared.b16 {%0,%1,%2,%3}, [%4];"
                 : "=r"(r[0]), "=r"(r[1]), "=r"(r[2]), "=r"(r[3]) : "r"(a));
}
__device__ __forceinline__ void mma16888(float* c, const uint32_t* a, const uint32_t* b) {
    asm volatile("mma.sync.aligned.m16n8k8.row.col.f32.tf32.tf32.f32 "
                 "{%0,%1,%2,%3}, {%4,%5,%6,%7}, {%8,%9}, {%0,%1,%2,%3};"
                 : "+f"(c[0]), "+f"(c[1]), "+f"(c[2]), "+f"(c[3])
                 : "r"(a[0]), "r"(a[1]), "r"(a[2]), "r"(a[3]), "r"(b[0]), "r"(b[1]));
}

// ---------------------------------------------------------------------------
// Kernel 1: counting sort by task (parallel warp-scan prefix).
// ---------------------------------------------------------------------------
__global__ void sort_rows_kernel(const void* __restrict__ task_ids_raw) {
    __shared__ int counts[NTASKS], scan[NTASKS], cursor[NTASKS];
    __shared__ int wtot, is64;
    const int tid = threadIdx.x;
    if (tid < NTASKS) counts[tid] = 0;
    if (tid == 0) is64 = 1;
    __syncthreads();
    const int* as32 = (const int*)task_ids_raw;
    int nz = 0;
    for (int i = tid; i < NROWS / 2; i += THREADS)
        if (as32[2 * i + 1] != 0) nz = 1;
    if (nz) atomicExch(&is64, 0);
    __syncthreads();
    const int wide = is64;
    for (int i = tid; i < NROWS; i += THREADS)
        atomicAdd(&counts[wide ? as32[2 * i] : as32[i]], 1);
    __syncthreads();
    if (tid < NTASKS) {
        const int lane = tid & 31;
        int s = counts[tid];
        #pragma unroll
        for (int d = 1; d < 32; d <<= 1) {
            int v = __shfl_up_sync(0xFFFFFFFF, s, d);
            if (lane >= d) s += v;
        }
        if (tid == 31) wtot = s;
        scan[tid] = s;
    }
    __syncthreads();
    if (tid < NTASKS) {
        int excl = scan[tid] + ((tid >= 32) ? wtot : 0) - counts[tid];
        cursor[tid] = excl;
        g_task_off[tid] = excl;
    }
    if (tid == 0) g_task_off[NTASKS] = NROWS;
    __syncthreads();
    for (int i = tid; i < NROWS; i += THREADS) {
        int t = wide ? as32[2 * i] : as32[i];
        g_row_order[atomicAdd(&cursor[t], 1)] = i;
    }
}

// ---------------------------------------------------------------------------
// Kernel 2: single-term tf32 GEMM, cp.async pipeline + ldmatrix A fragments.
// grid = (4, 64), 256 threads, 2 CTAs/SM. CTA tile 64m x 128n.
// ---------------------------------------------------------------------------
__global__ __launch_bounds__(THREADS, 2)
void task_gemm_tf32(const float* __restrict__ X, const float* __restrict__ W,
                    float* __restrict__ Out) {
    extern __shared__ __align__(16) char smem[];
    const uint32_t sb = smem_u32(smem);

    const int t    = blockIdx.y;
    const int r0   = g_task_off[t];
    const int r1   = g_task_off[t + 1];
    if (r0 >= r1) return;
    const int col0 = blockIdx.x * NTILE;

    const int tid = threadIdx.x, lane = tid & 31, wid = tid >> 5;
    // producer roles: am = A row / B k-row; q = quad
    const int am = tid >> 2;
    const int q  = tid & 3;

    const float* __restrict__ Wt = W + (size_t)t * INSZ * OUTSZ + col0;

    // consumer roles: 8 warps = 2m x 4n, warp tile 32m x 32n
    const int m0w = (wid & 1) * 32;
    const int n0w = (wid >> 1) * 32;
    const int g8  = lane >> 2;
    const int t4  = lane & 3;
    // ldmatrix lane address decomposition for A tiles
    const int mrow = m0w + ((lane >> 3) & 1) * 8 + (lane & 7);
    const int kadd = (lane >> 4) * 4;

    for (int base = r0; base < r1; base += MT) {
        const int nrows = min(MT, r1 - base);
        const bool avalid = am < nrows;
        const int asz = avalid ? 16 : 0;
        const float* __restrict__ aptr =
            avalid ? (X + (size_t)g_row_order[base + am] * INSZ) : X;

        auto issue = [&](int kt, int s) {
            const uint32_t stg = sb + s * STAGE;
            const float* asrc = aptr + kt * KT + q * 16;
            const uint32_t ao = stg + (am * AS + q * 16) * 4;
            #pragma unroll
            for (int j = 0; j < 4; j++)
                cpa16(ao + j * 16, asrc + j * 4, asz);
            const float* bsrc = Wt + (size_t)(kt * KT + am) * OUTSZ + q * 32;
            const uint32_t bo = stg + A_BYTES + (am * BS + q * 32) * 4;
            #pragma unroll
            for (int j = 0; j < 8; j++)
                cpa16(bo + j * 16, bsrc + j * 4, 16);
            cp_commit();
        };

        float acc[2][4][4];
        #pragma unroll
        for (int i = 0; i < 2; i++)
            #pragma unroll
            for (int j = 0; j < 4; j++)
                #pragma unroll
                for (int p = 0; p < 4; p++) acc[i][j][p] = 0.f;

        issue(0, 0);
        issue(1, 1);

        for (int kt = 0; kt < INSZ / KT; kt++) {
            if (kt < 7) cp_wait<1>(); else cp_wait<0>();
            __syncthreads();

            const uint32_t stg = sb + (kt & 1) * STAGE;
            const uint32_t abase = stg + (mrow * AS + kadd) * 4;
            const uint32_t bbase = stg + A_BYTES + (t4 * BS + n0w + g8) * 4;

            uint32_t af[2][2][4], bf[2][4][2];
            auto loadfrag = [&](int ks, int pb) {
                const int k0 = ks * 8;
                #pragma unroll
                for (int mt = 0; mt < 2; mt++)
                    ldm_x4(af[pb][mt], abase + (mt * 16 * AS + k0) * 4);
                #pragma unroll
                for (int nf = 0; nf < 4; nf++) {
                    const uint32_t r = bbase + (k0 * BS + nf * 8) * 4;
                    bf[pb][nf][0] = lds32(r);
                    bf[pb][nf][1] = lds32(r + 4 * BS * 4);
                }
            };

            loadfrag(0, 0);
            #pragma unroll
            for (int ks = 0; ks < 8; ks++) {
                const int cur = ks & 1;
                if (ks < 7) loadfrag(ks + 1, cur ^ 1);
                #pragma unroll
                for (int mt = 0; mt < 2; mt++)
                    #pragma unroll
                    for (int j = 0; j < 4; j++)
                        af[cur][mt][j] = cvt_tf32(af[cur][mt][j]);
                #pragma unroll
                for (int nf = 0; nf < 4; nf++) {
                    bf[cur][nf][0] = cvt_tf32(bf[cur][nf][0]);
                    bf[cur][nf][1] = cvt_tf32(bf[cur][nf][1]);
                }
                #pragma unroll
                for (int mt = 0; mt < 2; mt++)
                    #pragma unroll
                    for (int nf = 0; nf < 4; nf++)
                        mma16888(acc[mt][nf], af[cur][mt], bf[cur][nf]);
            }
            __syncthreads();
            if (kt + 2 < INSZ / KT) issue(kt + 2, kt & 1);
        }

        // epilogue: C frag m16n8: {c0,c1}@(g8, 2*t4), {c2,c3}@(g8+8, 2*t4)
        #pragma unroll
        for (int mt = 0; mt < 2; mt++) {
            const int ml0 = m0w + mt * 16 + g8;
            const int ml1 = ml0 + 8;
            const int o0 = (ml0 < nrows) ? g_row_order[base + ml0] : -1;
            const int o1 = (ml1 < nrows) ? g_row_order[base + ml1] : -1;
            #pragma unroll
            for (int nf = 0; nf < 4; nf++) {
                const int col = col0 + n0w + nf * 8 + t4 * 2;
                if (o0 >= 0)
                    *(float2*)(Out + (size_t)o0 * OUTSZ + col) =
                        make_float2(acc[mt][nf][0], acc[mt][nf][1]);
                if (o1 >= 0)
                    *(float2*)(Out + (size_t)o1 * OUTSZ + col) =
                        make_float2(acc[mt][nf][2], acc[mt][nf][3]);
            }
        }
    }
}

extern "C" void kernel_launch(void* const* d_in, const int* in_sizes, int n_in,
                              void* d_out, int out_size) {
    const float* X        = (const float*)d_in[0];   // [2048, 512] fp32
    const void*  task_ids = d_in[1];                 // [2048] int64 (or int32)
    const float* W        = (const float*)d_in[2];   // [64, 512, 512] fp32
    float*       Out      = (float*)d_out;           // [2048, 512] fp32

    cudaFuncSetAttribute(task_gemm_tf32, cudaFuncAttributeMaxDynamicSharedMemorySize, SMEM_TOTAL);
    sort_rows_kernel<<<1, THREADS>>>(task_ids);
    dim3 grid(OUTSZ / NTILE, NTASKS);
    task_gemm_tf32<<<grid, THREADS, SMEM_TOTAL>>>(X, W, Out);
}

// round 8
// speedup vs baseline: 1.6244x; 1.1716x over previous
#include <cuda_runtime.h>
#include <cstdint>

#define NTASKS 64
#define NROWS  2048
#define INSZ   512
#define OUTSZ  512
#define MT     64          // M rows per CTA tile
#define NTILE  128         // N cols per CTA
#define KT     32          // K per stage tile
#define NSTAGE 4
#define THREADS 256

// SMEM strides (floats), conflict-free for LDSM(A)/scalar(B)
#define AS 36              // 32 k + 4 pad  (36 mod 32 == 4)
#define BS 136             // 128 n + 8 pad (136 mod 32 == 8)
#define A_BYTES (MT * AS * 4)             // 9216
#define STAGE   (A_BYTES + KT * BS * 4)   // 9216 + 17408 = 26624
#define SMEM_TOTAL (NSTAGE * STAGE)       // 106496 -> 2 CTAs/SM

__device__ int g_row_order[NROWS];
__device__ int g_task_off[NTASKS + 1];

// ---------------- helpers ----------------
__device__ __forceinline__ uint32_t smem_u32(const void* p) {
    uint32_t a;
    asm("{ .reg .u64 t; cvta.to.shared.u64 t, %1; cvt.u32.u64 %0, t; }" : "=r"(a) : "l"(p));
    return a;
}
__device__ __forceinline__ uint32_t cvt_tf32(uint32_t bits) {
    uint32_t d;
    asm("cvt.rna.tf32.f32 %0, %1;" : "=r"(d) : "f"(__uint_as_float(bits)));
    return d;
}
__device__ __forceinline__ void cpa16(uint32_t dst, const void* src, int nbytes) {
    asm volatile("cp.async.cg.shared.global [%0], [%1], 16, %2;"
                 :: "r"(dst), "l"(src), "r"(nbytes) : "memory");
}
__device__ __forceinline__ void cp_commit() {
    asm volatile("cp.async.commit_group;" ::: "memory");
}
template <int N>
__device__ __forceinline__ void cp_wait() {
    asm volatile("cp.async.wait_group %0;" :: "n"(N) : "memory");
}
__device__ __forceinline__ uint32_t lds32(uint32_t a) {
    uint32_t v;
    asm volatile("ld.shared.b32 %0, [%1];" : "=r"(v) : "r"(a));
    return v;
}
__device__ __forceinline__ void ldm_x4(uint32_t* r, uint32_t a) {
    asm volatile("ldmatrix.sync.aligned.m8n8.x4.shared.b16 {%0,%1,%2,%3}, [%4];"
                 : "=r"(r[0]), "=r"(r[1]), "=r"(r[2]), "=r"(r[3]) : "r"(a));
}
__device__ __forceinline__ void mma16888(float* c, const uint32_t* a, const uint32_t* b) {
    asm volatile("mma.sync.aligned.m16n8k8.row.col.f32.tf32.tf32.f32 "
                 "{%0,%1,%2,%3}, {%4,%5,%6,%7}, {%8,%9}, {%0,%1,%2,%3};"
                 : "+f"(c[0]), "+f"(c[1]), "+f"(c[2]), "+f"(c[3])
                 : "r"(a[0]), "r"(a[1]), "r"(a[2]), "r"(a[3]), "r"(b[0]), "r"(b[1]));
}

// ---------------------------------------------------------------------------
// Kernel 1: counting sort by task (parallel warp-scan prefix).
// ---------------------------------------------------------------------------
__global__ void sort_rows_kernel(const void* __restrict__ task_ids_raw) {
    __shared__ int counts[NTASKS], scan[NTASKS], cursor[NTASKS];
    __shared__ int wtot, is64;
    const int tid = threadIdx.x;
    if (tid < NTASKS) counts[tid] = 0;
    if (tid == 0) is64 = 1;
    __syncthreads();
    const int* as32 = (const int*)task_ids_raw;
    int nz = 0;
    for (int i = tid; i < NROWS / 2; i += THREADS)
        if (as32[2 * i + 1] != 0) nz = 1;
    if (nz) atomicExch(&is64, 0);
    __syncthreads();
    const int wide = is64;
    for (int i = tid; i < NROWS; i += THREADS)
        atomicAdd(&counts[wide ? as32[2 * i] : as32[i]], 1);
    __syncthreads();
    if (tid < NTASKS) {
        const int lane = tid & 31;
        int s = counts[tid];
        #pragma unroll
        for (int d = 1; d < 32; d <<= 1) {
            int v = __shfl_up_sync(0xFFFFFFFF, s, d);
            if (lane >= d) s += v;
        }
        if (tid == 31) wtot = s;
        scan[tid] = s;
    }
    __syncthreads();
    if (tid < NTASKS) {
        int excl = scan[tid] + ((tid >= 32) ? wtot : 0) - counts[tid];
        cursor[tid] = excl;
        g_task_off[tid] = excl;
    }
    if (tid == 0) g_task_off[NTASKS] = NROWS;
    __syncthreads();
    for (int i = tid; i < NROWS; i += THREADS) {
        int t = wide ? as32[2 * i] : as32[i];
        g_row_order[atomicAdd(&cursor[t], 1)] = i;
    }
}

// ---------------------------------------------------------------------------
// Kernel 2: tf32 GEMM, 4-stage cp.async pipeline + ldmatrix A fragments.
// grid = (4, 64), 256 threads, 2 CTAs/SM. CTA tile 64m x 128n, KT=32.
// ---------------------------------------------------------------------------
__global__ __launch_bounds__(THREADS, 2)
void task_gemm_tf32(const float* __restrict__ X, const float* __restrict__ W,
                    float* __restrict__ Out) {
    extern __shared__ __align__(16) char smem[];
    const uint32_t sb = smem_u32(smem);

    const int t    = blockIdx.y;
    const int r0   = g_task_off[t];
    const int r1   = g_task_off[t + 1];
    if (r0 >= r1) return;
    const int col0 = blockIdx.x * NTILE;

    const int tid = threadIdx.x, lane = tid & 31, wid = tid >> 5;
    // producer roles
    const int am = tid >> 2;          // A row 0..63
    const int aq = tid & 3;           // A 8-float quad
    const int bm = tid >> 3;          // B k-row 0..31
    const int bq = tid & 7;           // B 16-float group

    const float* __restrict__ Wt = W + (size_t)t * INSZ * OUTSZ + col0;

    // consumer roles: 8 warps = 2m x 4n, warp tile 32m x 32n
    const int m0w = (wid & 1) * 32;
    const int n0w = (wid >> 1) * 32;
    const int g8  = lane >> 2;
    const int t4  = lane & 3;
    const int mrow = m0w + ((lane >> 3) & 1) * 8 + (lane & 7);
    const int kadd = (lane >> 4) * 4;

    const int NKT = INSZ / KT;   // 16

    for (int base = r0; base < r1; base += MT) {
        const int nrows = min(MT, r1 - base);
        const bool avalid = am < nrows;
        const int asz = avalid ? 16 : 0;
        const float* __restrict__ aptr =
            avalid ? (X + (size_t)g_row_order[base + am] * INSZ + aq * 8) : X;

        auto issue = [&](int kt) {
            const uint32_t stg = sb + (kt & (NSTAGE - 1)) * STAGE;
            const float* asrc = aptr + kt * KT;
            const uint32_t ao = stg + (am * AS + aq * 8) * 4;
            cpa16(ao,      asrc,     asz);
            cpa16(ao + 16, asrc + 4, asz);
            const float* bsrc = Wt + (size_t)(kt * KT + bm) * OUTSZ + bq * 16;
            const uint32_t bo = stg + A_BYTES + (bm * BS + bq * 16) * 4;
            #pragma unroll
            for (int j = 0; j < 4; j++)
                cpa16(bo + j * 16, bsrc + j * 4, 16);
            cp_commit();
        };

        float acc[2][4][4];
        #pragma unroll
        for (int i = 0; i < 2; i++)
            #pragma unroll
            for (int j = 0; j < 4; j++)
                #pragma unroll
                for (int p = 0; p < 4; p++) acc[i][j][p] = 0.f;

        issue(0); issue(1); issue(2);

        for (int kt = 0; kt < NKT; kt++) {
            if (kt < NKT - 2)      cp_wait<2>();
            else if (kt == NKT - 2) cp_wait<1>();
            else                    cp_wait<0>();
            __syncthreads();
            if (kt + 3 < NKT) issue(kt + 3);

            const uint32_t stg = sb + (kt & (NSTAGE - 1)) * STAGE;
            const uint32_t abase = stg + (mrow * AS + kadd) * 4;
            const uint32_t bbase = stg + A_BYTES + (t4 * BS + n0w + g8) * 4;

            uint32_t af[2][2][4], bf[2][4][2];
            auto loadfrag = [&](int ks, int pb) {
                const int k0 = ks * 8;
                #pragma unroll
                for (int mt = 0; mt < 2; mt++)
                    ldm_x4(af[pb][mt], abase + (mt * 16 * AS + k0) * 4);
                #pragma unroll
                for (int nf = 0; nf < 4; nf++) {
                    const uint32_t r = bbase + (k0 * BS + nf * 8) * 4;
                    bf[pb][nf][0] = lds32(r);
                    bf[pb][nf][1] = lds32(r + 4 * BS * 4);
                }
            };

            loadfrag(0, 0);
            #pragma unroll
            for (int ks = 0; ks < 4; ks++) {
                const int cur = ks & 1;
                if (ks < 3) loadfrag(ks + 1, cur ^ 1);
                #pragma unroll
                for (int mt = 0; mt < 2; mt++)
                    #pragma unroll
                    for (int j = 0; j < 4; j++)
                        af[cur][mt][j] = cvt_tf32(af[cur][mt][j]);
                #pragma unroll
                for (int nf = 0; nf < 4; nf++) {
                    bf[cur][nf][0] = cvt_tf32(bf[cur][nf][0]);
                    bf[cur][nf][1] = cvt_tf32(bf[cur][nf][1]);
                }
                #pragma unroll
                for (int mt = 0; mt < 2; mt++)
                    #pragma unroll
                    for (int nf = 0; nf < 4; nf++)
                        mma16888(acc[mt][nf], af[cur][mt], bf[cur][nf]);
            }
            __syncthreads();
        }

        // epilogue: C frag m16n8: {c0,c1}@(g8, 2*t4), {c2,c3}@(g8+8, 2*t4)
        #pragma unroll
        for (int mt = 0; mt < 2; mt++) {
            const int ml0 = m0w + mt * 16 + g8;
            const int ml1 = ml0 + 8;
            const int o0 = (ml0 < nrows) ? g_row_order[base + ml0] : -1;
            const int o1 = (ml1 < nrows) ? g_row_order[base + ml1] : -1;
            #pragma unroll
            for (int nf = 0; nf < 4; nf++) {
                const int col = col0 + n0w + nf * 8 + t4 * 2;
                if (o0 >= 0)
                    *(float2*)(Out + (size_t)o0 * OUTSZ + col) =
                        make_float2(acc[mt][nf][0], acc[mt][nf][1]);
                if (o1 >= 0)
                    *(float2*)(Out + (size_t)o1 * OUTSZ + col) =
                        make_float2(acc[mt][nf][2], acc[mt][nf][3]);
            }
        }
    }
}

extern "C" void kernel_launch(void* const* d_in, const int* in_sizes, int n_in,
                              void* d_out, int out_size) {
    const float* X        = (const float*)d_in[0];   // [2048, 512] fp32
    const void*  task_ids = d_in[1];                 // [2048] int64 (or int32)
    const float* W        = (const float*)d_in[2];   // [64, 512, 512] fp32
    float*       Out      = (float*)d_out;           // [2048, 512] fp32

    cudaFuncSetAttribute(task_gemm_tf32, cudaFuncAttributeMaxDynamicSharedMemorySize, SMEM_TOTAL);
    sort_rows_kernel<<<1, THREADS>>>(task_ids);
    dim3 grid(OUTSZ / NTILE, NTASKS);
    task_gemm_tf32<<<grid, THREADS, SMEM_TOTAL>>>(X, W, Out);
}